// round 13
// baseline (speedup 1.0000x reference)
#include <cuda_runtime.h>
#include <cuda_bf16.h>

// Problem constants: nw_out is [N=4, C=19, H=512, W=1024] float32.
#define NCH    19
#define NBAT   4
#define HH     512
#define WW     1024
#define HWP    (HH * WW)            // 524288 pixels per image
#define HWP2   (HWP / 2)            // 262144 float2 pairs per image-channel
#define NPIX   (NBAT * HWP)         // 2097152
#define NPAIR  (NPIX / 2)           // 1048576
#define IW_F   0.2f
#define GRID_BLOCKS 740             // 5 CTAs/SM x 148 SMs = one wave
#define NREP   4                    // replicated smem bins (cuts ATOMS replay)
#define RPAD   20                   // row pad: replicas 80B apart -> bank stagger

// Scratch accumulators. Zeroed at module load; fused finalize re-zeroes them.
__device__ float        g_sum[NCH] = {};
__device__ unsigned int g_cnt[NCH] = {};
__device__ unsigned int g_done     = 0;

__global__ __launch_bounds__(256, 5) void msiw_kernel(const float2* __restrict__ x2,
                                                      float* __restrict__ out) {
    __shared__ float        s_sum[NREP][RPAD];
    __shared__ unsigned int s_cnt[NREP][RPAD];
    if (threadIdx.x < NCH) {
#pragma unroll
        for (int r = 0; r < NREP; r++) {
            s_sum[r][threadIdx.x] = 0.0f;
            s_cnt[r][threadIdx.x] = 0u;
        }
    }
    __syncthreads();

    const int rep = threadIdx.x & (NREP - 1);      // 8 lanes per replica per warp
    // Packed log2(e) constant for the exp conversion (hoisted).
    unsigned long long L2E2;
    asm("mov.b64 %0, {%1, %2};" : "=l"(L2E2)
        : "f"(1.4426950408889634f), "f"(1.4426950408889634f));

    const int stride = GRID_BLOCKS * 256;          // in float2 pairs
    for (int q = blockIdx.x * blockDim.x + threadIdx.x; q < NPAIR; q += stride) {
        const int n   = q / HWP2;                  // batch index
        const int hw2 = q - n * HWP2;              // pair position within image
        const float2* base = x2 + (size_t)n * (NCH * HWP2) + hw2;

        // Load all 19 channels as float2. The max-tree below consumes ALL v,
        // so ptxas front-batches the 19 LDG.64 (R3/R8/R12-proven invariant).
        float2 v[NCH];
#pragma unroll
        for (int c = 0; c < NCH; c++) {
            v[c] = base[(size_t)c * HWP2];
        }

        // Max via FMNMX tree (depth 5): v[] dies at the subs right after ->
        // next iteration's loads can reuse those registers early (R12 win).
        float tx[10], ty[10];
#pragma unroll
        for (int c = 0; c < 9; c++) {
            tx[c] = fmaxf(v[2 * c].x, v[2 * c + 1].x);
            ty[c] = fmaxf(v[2 * c].y, v[2 * c + 1].y);
        }
        tx[9] = v[18].x; ty[9] = v[18].y;
#pragma unroll
        for (int c = 0; c < 5; c++) {
            tx[c] = fmaxf(tx[c], tx[c + 5]);
            ty[c] = fmaxf(ty[c], ty[c + 5]);
        }
        tx[0] = fmaxf(tx[0], tx[3]); ty[0] = fmaxf(ty[0], ty[3]);
        tx[1] = fmaxf(tx[1], tx[4]); ty[1] = fmaxf(ty[1], ty[4]);
        const float mx = fmaxf(fmaxf(tx[0], tx[1]), tx[2]);
        const float my = fmaxf(fmaxf(ty[0], ty[1]), ty[2]);

        // Exp-sums, packed f32x2: d = v - m (exact, feeds the d==0 idx test),
        // p = d * log2e (one packed mul replaces __expf's two scalar FMULs),
        // e = ex2.approx(p). idx chain gates only the atomics (off-path).
        unsigned long long m2, s1p, s2p;
        asm("mov.b64 %0, {%1, %2};" : "=l"(m2) : "f"(mx), "f"(my));
        asm("mov.b64 %0, {%1, %2};" : "=l"(s1p) : "f"(0.0f), "f"(0.0f));
        asm("mov.b64 %0, {%1, %2};" : "=l"(s2p) : "f"(0.0f), "f"(0.0f));
        int ix = 64, iy = 64;
#pragma unroll
        for (int c = 0; c < NCH; c++) {
            unsigned long long v2c, d2, p2, e2;
            asm("mov.b64 %0, {%1, %2};" : "=l"(v2c) : "f"(v[c].x), "f"(v[c].y));
            asm("sub.rn.f32x2 %0, %1, %2;" : "=l"(d2) : "l"(v2c), "l"(m2));
            float dx, dy;
            asm("mov.b64 {%0, %1}, %2;" : "=f"(dx), "=f"(dy) : "l"(d2));
            ix = min(ix, (dx == 0.0f) ? c : 64);
            iy = min(iy, (dy == 0.0f) ? c : 64);
            asm("mul.rn.f32x2 %0, %1, %2;" : "=l"(p2) : "l"(d2), "l"(L2E2));
            float px, py, ex, ey;
            asm("mov.b64 {%0, %1}, %2;" : "=f"(px), "=f"(py) : "l"(p2));
            asm("ex2.approx.ftz.f32 %0, %1;" : "=f"(ex) : "f"(px));
            asm("ex2.approx.ftz.f32 %0, %1;" : "=f"(ey) : "f"(py));
            asm("mov.b64 %0, {%1, %2};" : "=l"(e2) : "f"(ex), "f"(ey));
            asm("add.rn.f32x2 %0, %1, %2;" : "=l"(s1p) : "l"(s1p), "l"(e2));
            asm("fma.rn.f32x2 %0, %1, %2, %3;" : "=l"(s2p) : "l"(e2), "l"(e2), "l"(s2p));
        }
        float s1x, s1y, s2x, s2y;
        asm("mov.b64 {%0, %1}, %2;" : "=f"(s1x), "=f"(s1y) : "l"(s1p));
        asm("mov.b64 {%0, %1}, %2;" : "=f"(s2x), "=f"(s2y) : "l"(s2p));

        atomicAdd(&s_sum[rep][ix], __fdividef(s2x, s1x * s1x));
        atomicAdd(&s_sum[rep][iy], __fdividef(s2y, s1y * s1y));
        atomicAdd(&s_cnt[rep][ix], 1u);
        atomicAdd(&s_cnt[rep][iy], 1u);
    }

    __syncthreads();
    if (threadIdx.x < NCH) {
        float        fs = 0.0f;
        unsigned int cs = 0u;
#pragma unroll
        for (int r = 0; r < NREP; r++) {
            fs += s_sum[r][threadIdx.x];
            cs += s_cnt[r][threadIdx.x];
        }
        atomicAdd(&g_sum[threadIdx.x], fs);
        atomicAdd(&g_cnt[threadIdx.x], cs);
    }

    // ---- fused finalize: last block does the 19-term reduction ----
    __threadfence();
    __shared__ unsigned int s_last;
    if (threadIdx.x == 0) {
        unsigned int ticket = atomicAdd(&g_done, 1u);
        s_last = (ticket == GRID_BLOCKS - 1) ? 1u : 0u;
    }
    __syncthreads();
    if (s_last && threadIdx.x < 32) {
        int c = threadIdx.x;
        float partial = 0.0f;
        if (c < NCH) {
            float cnt   = (float)g_cnt[c];
            float scale = powf((float)NPIX, 1.0f - IW_F);        // Np^0.8
            float den   = fmaxf(powf(cnt, IW_F) * scale, 1.0f);  // max(hist^0.2*Np^0.8, 1)
            partial = g_sum[c] / den;
            g_sum[c] = 0.0f;                                     // reset for next replay
            g_cnt[c] = 0u;
        }
#pragma unroll
        for (int o = 16; o > 0; o >>= 1)
            partial += __shfl_down_sync(0xffffffffu, partial, o);
        if (c == 0) {
            out[0] = -partial / (float)(NBAT * NCH);
            g_done = 0;                                          // reset ticket
        }
    }
}

extern "C" void kernel_launch(void* const* d_in, const int* in_sizes, int n_in,
                              void* d_out, int out_size) {
    (void)in_sizes; (void)n_in; (void)out_size;
    const float2* x2 = (const float2*)d_in[0];
    float* out = (float*)d_out;

    // Single launch, one exact wave: 740 CTAs x 256 threads, 5 CTAs/SM.
    // R12 skeleton + packed-log2e ex2 (fewer scalar FMULs, shorter exp chain)
    // + 4-way replicated smem bins (fewer ATOMS replays on the LSU).
    msiw_kernel<<<GRID_BLOCKS, 256>>>(x2, out);
}